// round 6
// baseline (speedup 1.0000x reference)
#include <cuda_runtime.h>
#include <cuda_bf16.h>
#include <math_constants.h>
#include <cstdint>

// Problem dims
#define B_    4096
#define N0_   2048
#define N1_   1000
#define N1P   1024
#define N2_   500
#define N2P   512
#define N3_   100
#define C_    100
#define NDIM_ 3
#define NCLS_ 12

#define OUT_Y0 0
#define OUT_Y1 (B_ * NCLS_)
#define OUT_Y2 (B_ * NCLS_ + B_ * C_)

// ---------------- scratch ----------------
__device__ __nv_bfloat16 g_xhi[B_ * N0_];
__device__ __nv_bfloat16 g_xlo[B_ * N0_];
__device__ __nv_bfloat16 g_w1thi[N1P * N0_];
__device__ __nv_bfloat16 g_w1tlo[N1P * N0_];
__device__ __nv_bfloat16 g_h1hi[B_ * N1P];
__device__ __nv_bfloat16 g_h1lo[B_ * N1P];
__device__ __nv_bfloat16 g_w2thi[N2P * N1P];
__device__ __nv_bfloat16 g_w2tlo[N2P * N1P];
__device__ __nv_bfloat16 g_h2hi[B_ * N2P];
__device__ __nv_bfloat16 g_h2lo[B_ * N2P];
__device__ __nv_bfloat16 g_w3thi[128 * N2P];
__device__ __nv_bfloat16 g_w3tlo[128 * N2P];
__device__ int g_idx[B_];
__device__ int g_cnt[C_];
__device__ int g_off[C_ + 1];
__device__ int g_pos[C_];
__device__ int g_order[B_];

// ---------------- helpers ----------------
__device__ __forceinline__ uint32_t smem_u32(const void* p)
{
    uint32_t a;
    asm("{ .reg .u64 t; cvta.to.shared.u64 t, %1; cvt.u32.u64 %0, t; }" : "=r"(a) : "l"(p));
    return a;
}

__device__ __forceinline__ void cpasync16(uint32_t dst, const void* src)
{
    asm volatile("cp.async.cg.shared.global [%0], [%1], 16;" :: "r"(dst), "l"(src));
}

__device__ __forceinline__ void mma16816(float* c, const uint32_t* a, const uint32_t* b)
{
    asm volatile(
        "mma.sync.aligned.m16n8k16.row.col.f32.bf16.bf16.f32 "
        "{%0,%1,%2,%3}, {%4,%5,%6,%7}, {%8,%9}, {%0,%1,%2,%3};\n"
        : "+f"(c[0]), "+f"(c[1]), "+f"(c[2]), "+f"(c[3])
        : "r"(a[0]), "r"(a[1]), "r"(a[2]), "r"(a[3]), "r"(b[0]), "r"(b[1]));
}

__device__ __forceinline__ void ldsm4(uint32_t* r, uint32_t a)
{
    asm volatile("ldmatrix.sync.aligned.m8n8.x4.shared.b16 {%0,%1,%2,%3}, [%4];"
                 : "=r"(r[0]), "=r"(r[1]), "=r"(r[2]), "=r"(r[3]) : "r"(a));
}

// ---------------- preprocessing ----------------
__global__ void __launch_bounds__(256) split_kernel(
    const float* __restrict__ in, __nv_bfloat16* __restrict__ hi,
    __nv_bfloat16* __restrict__ lo, int n)
{
    int i = blockIdx.x * 256 + threadIdx.x;
    if (i >= n) return;
    float v = in[i];
    __nv_bfloat16 h = __float2bfloat16(v);
    hi[i] = h;
    lo[i] = __float2bfloat16(v - __bfloat162float(h));
}

// W [Kin][Nin] fp32 -> hi/lo [NP][KP] bf16 (transposed, zero-padded)
__global__ void __launch_bounds__(256) transpose_split_kernel(
    const float* __restrict__ in, __nv_bfloat16* __restrict__ hi,
    __nv_bfloat16* __restrict__ lo, int Kin, int Nin, int KP, int NP)
{
    __shared__ float t[32][33];
    int k0 = blockIdx.x * 32, n0 = blockIdx.y * 32;
    #pragma unroll
    for (int j = 0; j < 4; ++j) {
        int k = k0 + threadIdx.y + j * 8, n = n0 + threadIdx.x;
        t[threadIdx.y + j * 8][threadIdx.x] = (k < Kin && n < Nin) ? in[(size_t)k * Nin + n] : 0.f;
    }
    __syncthreads();
    #pragma unroll
    for (int j = 0; j < 4; ++j) {
        int n = n0 + threadIdx.y + j * 8, k = k0 + threadIdx.x;
        float v = t[threadIdx.x][threadIdx.y + j * 8];
        __nv_bfloat16 h = __float2bfloat16(v);
        hi[(size_t)n * KP + k] = h;
        lo[(size_t)n * KP + k] = __float2bfloat16(v - __bfloat162float(h));
    }
}

// ---------------- cp.async double-buffered split-bf16 mma GEMM ----------------
// A: hi/lo [M][K] bf16, B: hi/lo [N][K] bf16 (weights pre-transposed).
// Block tile 128x128x32, 8 warps (2m x 4n), warp tile 64x32.
// D = Ah*Bh + Ah*Bl + Al*Bh.
// EPI=0: fp32 out (ldC stride, pair-stores while gn+1 < Nvalid).
// EPI=1: bf16 hi/lo out, stride N, zeros beyond Nvalid.
#define STG_STRIDE 40960
#define OFF_AHI 0
#define OFF_ALO 10240
#define OFF_BHI 20480
#define OFF_BLO 30720
#define SMEM_MMA (2 * STG_STRIDE)

template <int EPI, bool RELU>
__global__ void __launch_bounds__(256, 2) mma_gemm_kernel(
    const __nv_bfloat16* __restrict__ Ahi, const __nv_bfloat16* __restrict__ Alo,
    const __nv_bfloat16* __restrict__ Bhi, const __nv_bfloat16* __restrict__ Blo,
    const float* __restrict__ bias,
    float* __restrict__ Cf, __nv_bfloat16* __restrict__ Chi, __nv_bfloat16* __restrict__ Clo,
    int ldC, int Nvalid, int N, int K)
{
    extern __shared__ __align__(16) char smem[];
    const uint32_t sb = smem_u32(smem);

    const int tid  = threadIdx.x;
    const int lane = tid & 31;
    const int w    = tid >> 5;
    const int wm   = (w & 1) * 64;
    const int wn   = (w >> 1) * 32;
    const int rowBase = blockIdx.y * 128;
    const int colBase = blockIdx.x * 128;

    float acc[4][4][4];
    #pragma unroll
    for (int mt = 0; mt < 4; ++mt)
        #pragma unroll
        for (int nt = 0; nt < 4; ++nt)
            #pragma unroll
            for (int q = 0; q < 4; ++q) acc[mt][nt][q] = 0.f;

    const int KT = K >> 5;
    const int lrow = tid >> 2;          // 0..63 per iter (2 iters -> 128 rows)
    const int lseg = tid & 3;

    auto load_stage = [&](int kt, int stage) {
        const uint32_t sbase = sb + stage * STG_STRIDE;
        #pragma unroll
        for (int it = 0; it < 2; ++it) {
            int row = lrow + it * 64;
            uint32_t doff = row * 80 + lseg * 16;
            size_t goffA = (size_t)(rowBase + row) * K + kt * 32 + lseg * 8;
            size_t goffB = (size_t)(colBase + row) * K + kt * 32 + lseg * 8;
            cpasync16(sbase + OFF_AHI + doff, Ahi + goffA);
            cpasync16(sbase + OFF_ALO + doff, Alo + goffA);
            cpasync16(sbase + OFF_BHI + doff, Bhi + goffB);
            cpasync16(sbase + OFF_BLO + doff, Blo + goffB);
        }
    };

    load_stage(0, 0);
    asm volatile("cp.async.commit_group;" ::: "memory");

    for (int kt = 0; kt < KT; ++kt) {
        const int cur = kt & 1;
        if (kt + 1 < KT) {
            load_stage(kt + 1, cur ^ 1);
            asm volatile("cp.async.commit_group;" ::: "memory");
            asm volatile("cp.async.wait_group 1;" ::: "memory");
        } else {
            asm volatile("cp.async.wait_group 0;" ::: "memory");
        }
        __syncthreads();

        const uint32_t sbase = sb + cur * STG_STRIDE;
        #pragma unroll
        for (int ks = 0; ks < 32; ks += 16) {
            uint32_t ah[4][4], al[4][4];
            #pragma unroll
            for (int mt = 0; mt < 4; ++mt) {
                uint32_t ad = sbase + OFF_AHI
                            + (wm + mt * 16 + (lane & 15)) * 80
                            + (ks + (lane >> 4) * 8) * 2;
                ldsm4(ah[mt], ad);
                ldsm4(al[mt], ad + (OFF_ALO - OFF_AHI));
            }
            uint32_t bh0[4], bh1[4], bl0[4], bl1[4];
            {
                uint32_t bd = sbase + OFF_BHI + (wn + lane) * 80 + ks * 2;
                ldsm4(bh0, bd);
                ldsm4(bh1, bd + 16);
                bd += (OFF_BLO - OFF_BHI);
                ldsm4(bl0, bd);
                ldsm4(bl1, bd + 16);
            }
            #pragma unroll
            for (int nt = 0; nt < 4; ++nt) {
                uint32_t bhp[2] = {bh0[nt], bh1[nt]};
                uint32_t blp[2] = {bl0[nt], bl1[nt]};
                #pragma unroll
                for (int mt = 0; mt < 4; ++mt) {
                    mma16816(acc[mt][nt], ah[mt], bhp);
                    mma16816(acc[mt][nt], ah[mt], blp);
                    mma16816(acc[mt][nt], al[mt], bhp);
                }
            }
        }
        __syncthreads();
    }

    // epilogue
    #pragma unroll
    for (int mt = 0; mt < 4; ++mt) {
        #pragma unroll
        for (int nt = 0; nt < 4; ++nt) {
            int gm0 = rowBase + wm + mt * 16 + (lane >> 2);
            int gn  = colBase + wn + nt * 8 + (lane & 3) * 2;
            bool valid = gn < Nvalid;
            float b0 = valid ? bias[gn] : 0.f;
            float b1 = valid ? bias[gn + 1] : 0.f;
            #pragma unroll
            for (int half = 0; half < 2; ++half) {
                int gm = gm0 + half * 8;
                float v0 = valid ? (acc[mt][nt][half * 2 + 0] + b0) : 0.f;
                float v1 = valid ? (acc[mt][nt][half * 2 + 1] + b1) : 0.f;
                if (RELU) { v0 = fmaxf(v0, 0.f); v1 = fmaxf(v1, 0.f); }
                if (EPI == 1) {
                    __nv_bfloat16 h0 = __float2bfloat16(v0);
                    __nv_bfloat16 h1 = __float2bfloat16(v1);
                    __nv_bfloat162 hp; hp.x = h0; hp.y = h1;
                    *reinterpret_cast<__nv_bfloat162*>(Chi + (size_t)gm * N + gn) = hp;
                    __nv_bfloat162 lp;
                    lp.x = __float2bfloat16(v0 - __bfloat162float(h0));
                    lp.y = __float2bfloat16(v1 - __bfloat162float(h1));
                    *reinterpret_cast<__nv_bfloat162*>(Clo + (size_t)gm * N + gn) = lp;
                } else {
                    if (gn + 1 < Nvalid) {
                        float2 o = make_float2(v0, v1);
                        *reinterpret_cast<float2*>(Cf + (size_t)gm * ldC + gn) = o;
                    }
                }
            }
        }
    }
}

// ---------------- y0 = x @ Wcat + bcat ----------------
__global__ void __launch_bounds__(256) y0_kernel(
    const float* __restrict__ x, const float* __restrict__ Wcat,
    const float* __restrict__ bcat, float* __restrict__ y0)
{
    __shared__ __align__(16) float xs[64][36];
    __shared__ float ws[32][NCLS_];

    const int tid  = threadIdx.x;
    const int row0 = blockIdx.x * 64;
    const int r    = tid >> 2;
    const int q    = tid & 3;

    float acc[3] = {0.f, 0.f, 0.f};

    for (int kt = 0; kt < N0_ / 32; ++kt) {
        #pragma unroll
        for (int i = 0; i < 2; ++i) {
            int id = tid + i * 256;
            int rr = id >> 3, seg = id & 7;
            float4 v = *reinterpret_cast<const float4*>(
                &x[(size_t)(row0 + rr) * N0_ + kt * 32 + seg * 4]);
            *reinterpret_cast<float4*>(&xs[rr][seg * 4]) = v;
        }
        #pragma unroll
        for (int i = 0; i < 2; ++i) {
            int id = tid + i * 256;
            if (id < 32 * NCLS_) ((float*)ws)[id] = Wcat[kt * 32 * NCLS_ + id];
        }
        __syncthreads();

        #pragma unroll 8
        for (int k = 0; k < 32; ++k) {
            float xv = xs[r][k];
            acc[0] += xv * ws[k][q];
            acc[1] += xv * ws[k][q + 4];
            acc[2] += xv * ws[k][q + 8];
        }
        __syncthreads();
    }

    float* out = y0 + (size_t)(row0 + r) * NCLS_;
    out[q]     = acc[0] + bcat[q];
    out[q + 4] = acc[1] + bcat[q + 4];
    out[q + 8] = acc[2] + bcat[q + 8];
}

// ---------------- argmax + counting sort ----------------
__global__ void zero_counts_kernel()
{
    int t = threadIdx.x;
    if (t < C_) g_cnt[t] = 0;
}

__global__ void argmax_kernel(const float* __restrict__ y1)
{
    const int warp = threadIdx.x >> 5, lane = threadIdx.x & 31;
    const int row = blockIdx.x * 4 + warp;
    const float* r = y1 + (size_t)row * C_;
    float bv = -CUDART_INF_F;
    int   bi = 0x7fffffff;
    for (int j = lane; j < C_; j += 32) {
        float v = r[j];
        if (v > bv || (v == bv && j < bi)) { bv = v; bi = j; }
    }
    #pragma unroll
    for (int o = 16; o; o >>= 1) {
        float ov = __shfl_down_sync(0xffffffffu, bv, o);
        int   oi = __shfl_down_sync(0xffffffffu, bi, o);
        if (ov > bv || (ov == bv && oi < bi)) { bv = ov; bi = oi; }
    }
    if (lane == 0) {
        g_idx[row] = bi;
        atomicAdd(&g_cnt[bi], 1);
    }
}

__global__ void prefix_kernel()
{
    if (threadIdx.x == 0) {
        int s = 0;
        for (int c = 0; c < C_; ++c) {
            g_off[c] = s;
            g_pos[c] = s;
            s += g_cnt[c];
        }
        g_off[C_] = s;
    }
}

__global__ void scatter_kernel()
{
    int b = blockIdx.x * 256 + threadIdx.x;
    int c = g_idx[b];
    int p = atomicAdd(&g_pos[c], 1);
    g_order[p] = b;
}

// ---------------- grouped expert kernel ----------------
#define EB_ROWS 32
#define EB_BK   32
#define NT      16

__global__ void __launch_bounds__(256) expert_kernel(
    const float* __restrict__ x,
    const float* __restrict__ We1, const float* __restrict__ be1,
    const float* __restrict__ We2, const float* __restrict__ be2,
    float* __restrict__ y2out)
{
    const int c     = blockIdx.y;
    const int chunk = blockIdx.x;
    const int start = g_off[c] + chunk * EB_ROWS;
    const int end   = g_off[c + 1];
    if (start >= end) return;

    __shared__ int   rs[EB_ROWS];
    __shared__ float Xs[EB_ROWS][EB_BK + 1];
    __shared__ float Ws[EB_BK * N3_ + 64];
    __shared__ float He[EB_ROWS][N3_ + 1];
    __shared__ float W2s[N3_ * NDIM_ + 4];

    const int tid  = threadIdx.x;
    const int lane = tid & 31;
    const int warp = tid >> 5;

    if (tid < EB_ROWS) rs[tid] = (start + tid < end) ? g_order[start + tid] : -1;
    for (int i = tid; i < N3_ * NDIM_; i += 256) W2s[i] = We2[(size_t)c * N3_ * NDIM_ + i];
    __syncthreads();

    const int nBase = warp * NT;
    float acc[NT];
    #pragma unroll
    for (int j = 0; j < NT; ++j) acc[j] = 0.f;

    const float* W1c = We1 + (size_t)c * N0_ * N3_;
    const float4* Ws4 = reinterpret_cast<const float4*>(Ws);

    for (int kt = 0; kt < N0_ / EB_BK; ++kt) {
        {
            int r  = tid >> 3;
            int k4 = (tid & 7) * 4;
            int rb = rs[r];
            float4 v = make_float4(0.f, 0.f, 0.f, 0.f);
            if (rb >= 0)
                v = *reinterpret_cast<const float4*>(&x[(size_t)rb * N0_ + kt * EB_BK + k4]);
            Xs[r][k4 + 0] = v.x; Xs[r][k4 + 1] = v.y;
            Xs[r][k4 + 2] = v.z; Xs[r][k4 + 3] = v.w;
        }
        {
            const float4* src = reinterpret_cast<const float4*>(W1c + (size_t)kt * EB_BK * N3_);
            float4* dst = reinterpret_cast<float4*>(Ws);
            #pragma unroll
            for (int i = 0; i < 4; ++i) {
                int id = tid + i * 256;
                if (id < (EB_BK * N3_) / 4) dst[id] = src[id];
            }
        }
        __syncthreads();

        #pragma unroll 4
        for (int k = 0; k < EB_BK; ++k) {
            float a = Xs[lane][k];
            #pragma unroll
            for (int j4 = 0; j4 < NT / 4; ++j4) {
                float4 wv = Ws4[(k * N3_ + nBase) / 4 + j4];
                acc[j4 * 4 + 0] += a * wv.x;
                acc[j4 * 4 + 1] += a * wv.y;
                acc[j4 * 4 + 2] += a * wv.z;
                acc[j4 * 4 + 3] += a * wv.w;
            }
        }
        __syncthreads();
    }

    #pragma unroll
    for (int j = 0; j < NT; ++j) {
        int n = nBase + j;
        if (n < N3_)
            He[lane][n] = fmaxf(acc[j] + be1[(size_t)c * N3_ + n], 0.f);
    }
    __syncthreads();

    if (tid < EB_ROWS * NDIM_) {
        int r = tid / NDIM_, d = tid % NDIM_;
        int rb = rs[r];
        if (rb >= 0) {
            float s = 0.f;
            #pragma unroll 4
            for (int k = 0; k < N3_; ++k) s += He[r][k] * W2s[k * NDIM_ + d];
            y2out[(size_t)rb * NDIM_ + d] = s + be2[(size_t)c * NDIM_ + d];
        }
    }
}

// ---------------- launch ----------------
extern "C" void kernel_launch(void* const* d_in, const int* in_sizes, int n_in,
                              void* d_out, int out_size)
{
    const float* x    = (const float*)d_in[0];
    const float* Wcat = (const float*)d_in[1];
    const float* bcat = (const float*)d_in[2];
    const float* Wb1  = (const float*)d_in[3];
    const float* bb1  = (const float*)d_in[4];
    const float* Wb2  = (const float*)d_in[5];
    const float* bb2  = (const float*)d_in[6];
    const float* Wb3  = (const float*)d_in[7];
    const float* bb3  = (const float*)d_in[8];
    const float* We1  = (const float*)d_in[9];
    const float* be1  = (const float*)d_in[10];
    const float* We2  = (const float*)d_in[11];
    const float* be2  = (const float*)d_in[12];
    float* out = (float*)d_out;

    __nv_bfloat16 *xhi, *xlo, *w1thi, *w1tlo, *h1hi, *h1lo;
    __nv_bfloat16 *w2thi, *w2tlo, *h2hi, *h2lo, *w3thi, *w3tlo;
    cudaGetSymbolAddress((void**)&xhi,   g_xhi);
    cudaGetSymbolAddress((void**)&xlo,   g_xlo);
    cudaGetSymbolAddress((void**)&w1thi, g_w1thi);
    cudaGetSymbolAddress((void**)&w1tlo, g_w1tlo);
    cudaGetSymbolAddress((void**)&h1hi,  g_h1hi);
    cudaGetSymbolAddress((void**)&h1lo,  g_h1lo);
    cudaGetSymbolAddress((void**)&w2thi, g_w2thi);
    cudaGetSymbolAddress((void**)&w2tlo, g_w2tlo);
    cudaGetSymbolAddress((void**)&h2hi,  g_h2hi);
    cudaGetSymbolAddress((void**)&h2lo,  g_h2lo);
    cudaGetSymbolAddress((void**)&w3thi, g_w3thi);
    cudaGetSymbolAddress((void**)&w3tlo, g_w3tlo);

    cudaFuncSetAttribute(mma_gemm_kernel<1, true>,
                         cudaFuncAttributeMaxDynamicSharedMemorySize, SMEM_MMA);
    cudaFuncSetAttribute(mma_gemm_kernel<0, false>,
                         cudaFuncAttributeMaxDynamicSharedMemorySize, SMEM_MMA);

    // preprocessing
    split_kernel<<<(B_ * N0_ + 255) / 256, 256>>>(x, xhi, xlo, B_ * N0_);
    {
        dim3 blk(32, 8);
        transpose_split_kernel<<<dim3(N0_ / 32, N1P / 32), blk>>>(Wb1, w1thi, w1tlo, N0_, N1_, N0_, N1P);
        transpose_split_kernel<<<dim3(N1P / 32, N2P / 32), blk>>>(Wb2, w2thi, w2tlo, N1_, N2_, N1P, N2P);
        transpose_split_kernel<<<dim3(N2P / 32, 128 / 32), blk>>>(Wb3, w3thi, w3tlo, N2_, C_, N2P, 128);
    }

    // bin head on tensor cores (cp.async pipeline)
    mma_gemm_kernel<1, true><<<dim3(N1P / 128, B_ / 128), 256, SMEM_MMA>>>(
        xhi, xlo, w1thi, w1tlo, bb1, nullptr, h1hi, h1lo, 0, N1_, N1P, N0_);
    mma_gemm_kernel<1, true><<<dim3(N2P / 128, B_ / 128), 256, SMEM_MMA>>>(
        h1hi, h1lo, w2thi, w2tlo, bb2, nullptr, h2hi, h2lo, 0, N2_, N2P, N1P);
    mma_gemm_kernel<0, false><<<dim3(1, B_ / 128), 256, SMEM_MMA>>>(
        h2hi, h2lo, w3thi, w3tlo, bb3, out + OUT_Y1, nullptr, nullptr, C_, C_, 128, N2P);

    // category head
    y0_kernel<<<B_ / 64, 256>>>(x, Wcat, bcat, out + OUT_Y0);

    // argmax + counting sort
    zero_counts_kernel<<<1, 128>>>();
    argmax_kernel<<<B_ / 4, 128>>>(out + OUT_Y1);
    prefix_kernel<<<1, 32>>>();
    scatter_kernel<<<B_ / 256, 256>>>();

    // selected-expert evaluation
    {
        dim3 grid(B_ / EB_ROWS, C_);
        expert_kernel<<<grid, 256>>>(x, We1, be1, We2, be2, out + OUT_Y2);
    }
}

// round 7
// speedup vs baseline: 1.1178x; 1.1178x over previous
#include <cuda_runtime.h>
#include <cuda_bf16.h>
#include <math_constants.h>
#include <cstdint>

// Problem dims
#define B_    4096
#define N0_   2048
#define N1_   1000
#define N1P   1024
#define N1E   (N1P + 64)      // GEMM1 B-matrix rows incl. fused y0 (Wcat) block
#define N2_   500
#define N2P   512
#define N3_   100
#define C_    100
#define NDIM_ 3
#define NCLS_ 12

#define OUT_Y0 0
#define OUT_Y1 (B_ * NCLS_)
#define OUT_Y2 (B_ * NCLS_ + B_ * C_)

// ---------------- scratch ----------------
__device__ __nv_bfloat16 g_xhi[B_ * N0_];
__device__ __nv_bfloat16 g_xlo[B_ * N0_];
__device__ __nv_bfloat16 g_w1thi[N1E * N0_];
__device__ __nv_bfloat16 g_w1tlo[N1E * N0_];
__device__ __nv_bfloat16 g_h1hi[B_ * N1P];
__device__ __nv_bfloat16 g_h1lo[B_ * N1P];
__device__ __nv_bfloat16 g_w2thi[N2P * N1P];
__device__ __nv_bfloat16 g_w2tlo[N2P * N1P];
__device__ __nv_bfloat16 g_h2hi[B_ * N2P];
__device__ __nv_bfloat16 g_h2lo[B_ * N2P];
__device__ __nv_bfloat16 g_w3thi[128 * N2P];
__device__ __nv_bfloat16 g_w3tlo[128 * N2P];
__device__ int g_idx[B_];
__device__ int g_cnt[C_];
__device__ int g_off[C_ + 1];
__device__ int g_pos[C_];
__device__ int g_order[B_];

// ---------------- helpers ----------------
__device__ __forceinline__ uint32_t smem_u32(const void* p)
{
    uint32_t a;
    asm("{ .reg .u64 t; cvta.to.shared.u64 t, %1; cvt.u32.u64 %0, t; }" : "=r"(a) : "l"(p));
    return a;
}

__device__ __forceinline__ void cpasync16(uint32_t dst, const void* src)
{
    asm volatile("cp.async.cg.shared.global [%0], [%1], 16;" :: "r"(dst), "l"(src));
}

__device__ __forceinline__ void mma16816(float* c, const uint32_t* a, const uint32_t* b)
{
    asm volatile(
        "mma.sync.aligned.m16n8k16.row.col.f32.bf16.bf16.f32 "
        "{%0,%1,%2,%3}, {%4,%5,%6,%7}, {%8,%9}, {%0,%1,%2,%3};\n"
        : "+f"(c[0]), "+f"(c[1]), "+f"(c[2]), "+f"(c[3])
        : "r"(a[0]), "r"(a[1]), "r"(a[2]), "r"(a[3]), "r"(b[0]), "r"(b[1]));
}

__device__ __forceinline__ void ldsm4(uint32_t* r, uint32_t a)
{
    asm volatile("ldmatrix.sync.aligned.m8n8.x4.shared.b16 {%0,%1,%2,%3}, [%4];"
                 : "=r"(r[0]), "=r"(r[1]), "=r"(r[2]), "=r"(r[3]) : "r"(a));
}

// ---------------- preprocessing ----------------
__global__ void __launch_bounds__(256) split_kernel(
    const float* __restrict__ in, __nv_bfloat16* __restrict__ hi,
    __nv_bfloat16* __restrict__ lo, int n4)
{
    int i = blockIdx.x * 256 + threadIdx.x;
    if (i >= n4) return;
    float4 v = reinterpret_cast<const float4*>(in)[i];
    __nv_bfloat16 h0 = __float2bfloat16(v.x);
    __nv_bfloat16 h1 = __float2bfloat16(v.y);
    __nv_bfloat16 h2 = __float2bfloat16(v.z);
    __nv_bfloat16 h3 = __float2bfloat16(v.w);
    __nv_bfloat162 hp0; hp0.x = h0; hp0.y = h1;
    __nv_bfloat162 hp1; hp1.x = h2; hp1.y = h3;
    reinterpret_cast<__nv_bfloat162*>(hi)[i * 2 + 0] = hp0;
    reinterpret_cast<__nv_bfloat162*>(hi)[i * 2 + 1] = hp1;
    __nv_bfloat162 lp0, lp1;
    lp0.x = __float2bfloat16(v.x - __bfloat162float(h0));
    lp0.y = __float2bfloat16(v.y - __bfloat162float(h1));
    lp1.x = __float2bfloat16(v.z - __bfloat162float(h2));
    lp1.y = __float2bfloat16(v.w - __bfloat162float(h3));
    reinterpret_cast<__nv_bfloat162*>(lo)[i * 2 + 0] = lp0;
    reinterpret_cast<__nv_bfloat162*>(lo)[i * 2 + 1] = lp1;
}

// W [Kin][Nin] fp32 -> hi/lo [NP][KP] bf16 (transposed, zero-padded)
__global__ void __launch_bounds__(256) transpose_split_kernel(
    const float* __restrict__ in, __nv_bfloat16* __restrict__ hi,
    __nv_bfloat16* __restrict__ lo, int Kin, int Nin, int KP, int NP)
{
    __shared__ float t[32][33];
    int k0 = blockIdx.x * 32, n0 = blockIdx.y * 32;
    #pragma unroll
    for (int j = 0; j < 4; ++j) {
        int k = k0 + threadIdx.y + j * 8, n = n0 + threadIdx.x;
        t[threadIdx.y + j * 8][threadIdx.x] = (k < Kin && n < Nin) ? in[(size_t)k * Nin + n] : 0.f;
    }
    __syncthreads();
    #pragma unroll
    for (int j = 0; j < 4; ++j) {
        int n = n0 + threadIdx.y + j * 8, k = k0 + threadIdx.x;
        float v = t[threadIdx.x][threadIdx.y + j * 8];
        __nv_bfloat16 h = __float2bfloat16(v);
        hi[(size_t)n * KP + k] = h;
        lo[(size_t)n * KP + k] = __float2bfloat16(v - __bfloat162float(h));
    }
}

// ---------------- cp.async 3-stage split-bf16 mma GEMM (R5 shape) ----------------
// A: hi/lo [M][K] bf16, B: hi/lo [N][K] bf16.
// Block tile 128x64x32, 8 warps (4m x 2n), warp tile 32x32.
// D = Ah*Bh + Ah*Bl + Al*Bh.
// EPI=1: packed bf16 hi/lo out (stride strideH) for colBase<NB; fp32 y0 out
//        (12 cols, biasY, no relu) for colBase>=NB when Yf != nullptr.
// EPI=0: fp32 out, ldC stride, pair stores while gn+1 < Nvalid.
#define STAGE_SZ 30720            // A(hi,lo): 2*10240, B(hi,lo): 2*5120
#define A_LO_OFF 10240
#define B_HI_OFF 20480
#define B_LO_OFF 25600
#define SMEM_MMA (3 * STAGE_SZ)   // 92160

template <int EPI>
__global__ void __launch_bounds__(256, 2) mma_gemm_kernel(
    const __nv_bfloat16* __restrict__ Ahi, const __nv_bfloat16* __restrict__ Alo,
    const __nv_bfloat16* __restrict__ Bhi, const __nv_bfloat16* __restrict__ Blo,
    const float* __restrict__ bias, const float* __restrict__ biasY,
    float* __restrict__ Cf, __nv_bfloat16* __restrict__ Chi, __nv_bfloat16* __restrict__ Clo,
    float* __restrict__ Yf,
    int ldC, int Nvalid, int NB, int strideH, int K, int relu)
{
    extern __shared__ __align__(16) char smem[];
    const uint32_t sb = smem_u32(smem);

    const int tid  = threadIdx.x;
    const int lane = tid & 31;
    const int w    = tid >> 5;
    const int wm   = (w >> 1) * 32;
    const int wn   = (w & 1) * 32;
    const int rowBase = blockIdx.y * 128;
    const int colBase = blockIdx.x * 64;

    float acc[2][4][4];
    #pragma unroll
    for (int mt = 0; mt < 2; ++mt)
        #pragma unroll
        for (int nt = 0; nt < 4; ++nt)
            #pragma unroll
            for (int q = 0; q < 4; ++q) acc[mt][nt][q] = 0.f;

    const int KT = K >> 5;
    const int arow = tid >> 2;      // 0..63 (+64 second iter) for A; 0..63 for B
    const int aseg = tid & 3;

    auto load_stage = [&](int kt, int stage) {
        const uint32_t sbase = sb + stage * STAGE_SZ;
        #pragma unroll
        for (int it = 0; it < 2; ++it) {
            int row = arow + it * 64;
            uint32_t doff = row * 80 + aseg * 16;
            size_t goff = (size_t)(rowBase + row) * K + kt * 32 + aseg * 8;
            cpasync16(sbase + doff, Ahi + goff);
            cpasync16(sbase + A_LO_OFF + doff, Alo + goff);
        }
        {
            int row = arow;
            uint32_t doff = row * 80 + aseg * 16;
            size_t goff = (size_t)(colBase + row) * K + kt * 32 + aseg * 8;
            cpasync16(sbase + B_HI_OFF + doff, Bhi + goff);
            cpasync16(sbase + B_LO_OFF + doff, Blo + goff);
        }
    };

    load_stage(0, 0);
    asm volatile("cp.async.commit_group;" ::: "memory");
    load_stage(1, 1);
    asm volatile("cp.async.commit_group;" ::: "memory");

    int stage = 0;
    for (int kt = 0; kt < KT; ++kt) {
        if (kt + 1 < KT)
            asm volatile("cp.async.wait_group 1;" ::: "memory");
        else
            asm volatile("cp.async.wait_group 0;" ::: "memory");
        __syncthreads();

        if (kt + 2 < KT) {
            int ns = stage + 2; if (ns >= 3) ns -= 3;
            load_stage(kt + 2, ns);
            asm volatile("cp.async.commit_group;" ::: "memory");
        }

        const uint32_t sbase = sb + stage * STAGE_SZ;
        #pragma unroll
        for (int ks = 0; ks < 32; ks += 16) {
            uint32_t ah[2][4], al[2][4];
            #pragma unroll
            for (int mt = 0; mt < 2; ++mt) {
                uint32_t ad = sbase + (wm + mt * 16 + (lane & 15)) * 80
                            + (ks + (lane >> 4) * 8) * 2;
                ldsm4(ah[mt], ad);
                ldsm4(al[mt], ad + A_LO_OFF);
            }
            uint32_t bh0[4], bh1[4], bl0[4], bl1[4];
            {
                uint32_t bd = sbase + B_HI_OFF + (wn + lane) * 80 + ks * 2;
                ldsm4(bh0, bd);
                ldsm4(bh1, bd + 16);
                bd += (B_LO_OFF - B_HI_OFF);
                ldsm4(bl0, bd);
                ldsm4(bl1, bd + 16);
            }
            #pragma unroll
            for (int nt = 0; nt < 4; ++nt) {
                uint32_t bhp[2] = {bh0[nt], bh1[nt]};
                uint32_t blp[2] = {bl0[nt], bl1[nt]};
                #pragma unroll
                for (int mt = 0; mt < 2; ++mt) {
                    mma16816(acc[mt][nt], ah[mt], bhp);
                    mma16816(acc[mt][nt], ah[mt], blp);
                    mma16816(acc[mt][nt], al[mt], bhp);
                }
            }
        }
        __syncthreads();
        ++stage; if (stage == 3) stage = 0;
    }

    // epilogue
    const bool yblock = (EPI == 1) && (Yf != nullptr) && (colBase >= NB);
    #pragma unroll
    for (int mt = 0; mt < 2; ++mt) {
        #pragma unroll
        for (int nt = 0; nt < 4; ++nt) {
            int gm0 = rowBase + wm + mt * 16 + (lane >> 2);
            int gn  = colBase + wn + nt * 8 + (lane & 3) * 2;
            if (yblock) {
                int gy = gn - NB;
                if (gy < NCLS_) {
                    float b0 = biasY[gy], b1 = biasY[gy + 1];
                    #pragma unroll
                    for (int half = 0; half < 2; ++half) {
                        int gm = gm0 + half * 8;
                        float2 o = make_float2(acc[mt][nt][half * 2 + 0] + b0,
                                               acc[mt][nt][half * 2 + 1] + b1);
                        *reinterpret_cast<float2*>(Yf + (size_t)gm * NCLS_ + gy) = o;
                    }
                }
            } else {
                bool valid = gn < Nvalid;
                float b0 = valid ? bias[gn] : 0.f;
                float b1 = valid ? bias[gn + 1] : 0.f;
                #pragma unroll
                for (int half = 0; half < 2; ++half) {
                    int gm = gm0 + half * 8;
                    float v0 = valid ? (acc[mt][nt][half * 2 + 0] + b0) : 0.f;
                    float v1 = valid ? (acc[mt][nt][half * 2 + 1] + b1) : 0.f;
                    if (relu) { v0 = fmaxf(v0, 0.f); v1 = fmaxf(v1, 0.f); }
                    if (EPI == 1) {
                        __nv_bfloat16 h0 = __float2bfloat16(v0);
                        __nv_bfloat16 h1 = __float2bfloat16(v1);
                        __nv_bfloat162 hp; hp.x = h0; hp.y = h1;
                        *reinterpret_cast<__nv_bfloat162*>(Chi + (size_t)gm * strideH + gn) = hp;
                        __nv_bfloat162 lp;
                        lp.x = __float2bfloat16(v0 - __bfloat162float(h0));
                        lp.y = __float2bfloat16(v1 - __bfloat162float(h1));
                        *reinterpret_cast<__nv_bfloat162*>(Clo + (size_t)gm * strideH + gn) = lp;
                    } else {
                        if (gn + 1 < Nvalid) {
                            float2 o = make_float2(v0, v1);
                            *reinterpret_cast<float2*>(Cf + (size_t)gm * ldC + gn) = o;
                        }
                    }
                }
            }
        }
    }
}

// ---------------- argmax + counting sort ----------------
__global__ void zero_counts_kernel()
{
    int t = threadIdx.x;
    if (t < C_) g_cnt[t] = 0;
}

__global__ void argmax_kernel(const float* __restrict__ y1)
{
    const int warp = threadIdx.x >> 5, lane = threadIdx.x & 31;
    const int row = blockIdx.x * 4 + warp;
    const float* r = y1 + (size_t)row * C_;
    float bv = -CUDART_INF_F;
    int   bi = 0x7fffffff;
    for (int j = lane; j < C_; j += 32) {
        float v = r[j];
        if (v > bv || (v == bv && j < bi)) { bv = v; bi = j; }
    }
    #pragma unroll
    for (int o = 16; o; o >>= 1) {
        float ov = __shfl_down_sync(0xffffffffu, bv, o);
        int   oi = __shfl_down_sync(0xffffffffu, bi, o);
        if (ov > bv || (ov == bv && oi < bi)) { bv = ov; bi = oi; }
    }
    if (lane == 0) {
        g_idx[row] = bi;
        atomicAdd(&g_cnt[bi], 1);
    }
}

__global__ void prefix_kernel()
{
    if (threadIdx.x == 0) {
        int s = 0;
        for (int c = 0; c < C_; ++c) {
            g_off[c] = s;
            g_pos[c] = s;
            s += g_cnt[c];
        }
        g_off[C_] = s;
    }
}

__global__ void scatter_kernel()
{
    int b = blockIdx.x * 256 + threadIdx.x;
    int c = g_idx[b];
    int p = atomicAdd(&g_pos[c], 1);
    g_order[p] = b;
}

// ---------------- grouped expert kernel ----------------
#define EB_ROWS 32
#define EB_BK   32
#define NT      16

__global__ void __launch_bounds__(256) expert_kernel(
    const float* __restrict__ x,
    const float* __restrict__ We1, const float* __restrict__ be1,
    const float* __restrict__ We2, const float* __restrict__ be2,
    float* __restrict__ y2out)
{
    const int c     = blockIdx.y;
    const int chunk = blockIdx.x;
    const int start = g_off[c] + chunk * EB_ROWS;
    const int end   = g_off[c + 1];
    if (start >= end) return;

    __shared__ int   rs[EB_ROWS];
    __shared__ float Xs[EB_ROWS][EB_BK + 1];
    __shared__ float Ws[EB_BK * N3_ + 64];
    __shared__ float He[EB_ROWS][N3_ + 1];
    __shared__ float W2s[N3_ * NDIM_ + 4];

    const int tid  = threadIdx.x;
    const int lane = tid & 31;
    const int warp = tid >> 5;

    if (tid < EB_ROWS) rs[tid] = (start + tid < end) ? g_order[start + tid] : -1;
    for (int i = tid; i < N3_ * NDIM_; i += 256) W2s[i] = We2[(size_t)c * N3_ * NDIM_ + i];
    __syncthreads();

    const int nBase = warp * NT;
    float acc[NT];
    #pragma unroll
    for (int j = 0; j < NT; ++j) acc[j] = 0.f;

    const float* W1c = We1 + (size_t)c * N0_ * N3_;
    const float4* Ws4 = reinterpret_cast<const float4*>(Ws);

    for (int kt = 0; kt < N0_ / EB_BK; ++kt) {
        {
            int r  = tid >> 3;
            int k4 = (tid & 7) * 4;
            int rb = rs[r];
            float4 v = make_float4(0.f, 0.f, 0.f, 0.f);
            if (rb >= 0)
                v = *reinterpret_cast<const float4*>(&x[(size_t)rb * N0_ + kt * EB_BK + k4]);
            Xs[r][k4 + 0] = v.x; Xs[r][k4 + 1] = v.y;
            Xs[r][k4 + 2] = v.z; Xs[r][k4 + 3] = v.w;
        }
        {
            const float4* src = reinterpret_cast<const float4*>(W1c + (size_t)kt * EB_BK * N3_);
            float4* dst = reinterpret_cast<float4*>(Ws);
            #pragma unroll
            for (int i = 0; i < 4; ++i) {
                int id = tid + i * 256;
                if (id < (EB_BK * N3_) / 4) dst[id] = src[id];
            }
        }
        __syncthreads();

        #pragma unroll 4
        for (int k = 0; k < EB_BK; ++k) {
            float a = Xs[lane][k];
            #pragma unroll
            for (int j4 = 0; j4 < NT / 4; ++j4) {
                float4 wv = Ws4[(k * N3_ + nBase) / 4 + j4];
                acc[j4 * 4 + 0] += a * wv.x;
                acc[j4 * 4 + 1] += a * wv.y;
                acc[j4 * 4 + 2] += a * wv.z;
                acc[j4 * 4 + 3] += a * wv.w;
            }
        }
        __syncthreads();
    }

    #pragma unroll
    for (int j = 0; j < NT; ++j) {
        int n = nBase + j;
        if (n < N3_)
            He[lane][n] = fmaxf(acc[j] + be1[(size_t)c * N3_ + n], 0.f);
    }
    __syncthreads();

    if (tid < EB_ROWS * NDIM_) {
        int r = tid / NDIM_, d = tid % NDIM_;
        int rb = rs[r];
        if (rb >= 0) {
            float s = 0.f;
            #pragma unroll 4
            for (int k = 0; k < N3_; ++k) s += He[r][k] * W2s[k * NDIM_ + d];
            y2out[(size_t)rb * NDIM_ + d] = s + be2[(size_t)c * NDIM_ + d];
        }
    }
}

// ---------------- launch ----------------
extern "C" void kernel_launch(void* const* d_in, const int* in_sizes, int n_in,
                              void* d_out, int out_size)
{
    const float* x    = (const float*)d_in[0];
    const float* Wcat = (const float*)d_in[1];
    const float* bcat = (const float*)d_in[2];
    const float* Wb1  = (const float*)d_in[3];
    const float* bb1  = (const float*)d_in[4];
    const float* Wb2  = (const float*)d_in[5];
    const float* bb2  = (const float*)d_in[6];
    const float* Wb3  = (const float*)d_in[7];
    const float* bb3  = (const float*)d_in[8];
    const float* We1  = (const float*)d_in[9];
    const float* be1  = (const float*)d_in[10];
    const float* We2  = (const float*)d_in[11];
    const float* be2  = (const float*)d_in[12];
    float* out = (float*)d_out;

    __nv_bfloat16 *xhi, *xlo, *w1thi, *w1tlo, *h1hi, *h1lo;
    __nv_bfloat16 *w2thi, *w2tlo, *h2hi, *h2lo, *w3thi, *w3tlo;
    cudaGetSymbolAddress((void**)&xhi,   g_xhi);
    cudaGetSymbolAddress((void**)&xlo,   g_xlo);
    cudaGetSymbolAddress((void**)&w1thi, g_w1thi);
    cudaGetSymbolAddress((void**)&w1tlo, g_w1tlo);
    cudaGetSymbolAddress((void**)&h1hi,  g_h1hi);
    cudaGetSymbolAddress((void**)&h1lo,  g_h1lo);
    cudaGetSymbolAddress((void**)&w2thi, g_w2thi);
    cudaGetSymbolAddress((void**)&w2tlo, g_w2tlo);
    cudaGetSymbolAddress((void**)&h2hi,  g_h2hi);
    cudaGetSymbolAddress((void**)&h2lo,  g_h2lo);
    cudaGetSymbolAddress((void**)&w3thi, g_w3thi);
    cudaGetSymbolAddress((void**)&w3tlo, g_w3tlo);

    cudaFuncSetAttribute(mma_gemm_kernel<1>,
                         cudaFuncAttributeMaxDynamicSharedMemorySize, SMEM_MMA);
    cudaFuncSetAttribute(mma_gemm_kernel<0>,
                         cudaFuncAttributeMaxDynamicSharedMemorySize, SMEM_MMA);

    dim3 tblk(32, 8);
    const int BIG = 1 << 30;

    // 1: split x
    split_kernel<<<(B_ * N0_ / 4 + 255) / 256, 256>>>(x, xhi, xlo, B_ * N0_ / 4);
    // 2: Wb1^T -> w1t rows [0, 1024)
    transpose_split_kernel<<<dim3(N0_ / 32, N1P / 32), tblk>>>(Wb1, w1thi, w1tlo, N0_, N1_, N0_, N1P);
    // 3: Wcat^T -> w1t rows [1024, 1088)
    transpose_split_kernel<<<dim3(N0_ / 32, 64 / 32), tblk>>>(
        Wcat, w1thi + (size_t)N1P * N0_, w1tlo + (size_t)N1P * N0_, N0_, NCLS_, N0_, 64);
    // 4: GEMM1 (h1 + fused y0)  <-- profiled launch
    mma_gemm_kernel<1><<<dim3(N1E / 64, B_ / 128), 256, SMEM_MMA>>>(
        xhi, xlo, w1thi, w1tlo, bb1, bcat,
        nullptr, h1hi, h1lo, out + OUT_Y0,
        0, N1_, N1P, N1P, N0_, 1);
    // 5: Wb2^T
    transpose_split_kernel<<<dim3(N1P / 32, N2P / 32), tblk>>>(Wb2, w2thi, w2tlo, N1_, N2_, N1P, N2P);
    // 6: GEMM2
    mma_gemm_kernel<1><<<dim3(N2P / 64, B_ / 128), 256, SMEM_MMA>>>(
        h1hi, h1lo, w2thi, w2tlo, bb2, nullptr,
        nullptr, h2hi, h2lo, nullptr,
        0, N2_, BIG, N2P, N1P, 1);
    // 7: Wb3^T
    transpose_split_kernel<<<dim3(N2P / 32, 128 / 32), tblk>>>(Wb3, w3thi, w3tlo, N2_, C_, N2P, 128);
    // 8: GEMM3 -> y1 fp32
    mma_gemm_kernel<0><<<dim3(128 / 64, B_ / 128), 256, SMEM_MMA>>>(
        h2hi, h2lo, w3thi, w3tlo, bb3, nullptr,
        out + OUT_Y1, nullptr, nullptr, nullptr,
        C_, C_, BIG, 0, N2P, 0);

    // argmax + counting sort
    zero_counts_kernel<<<1, 128>>>();
    argmax_kernel<<<B_ / 4, 128>>>(out + OUT_Y1);
    prefix_kernel<<<1, 32>>>();
    scatter_kernel<<<B_ / 256, 256>>>();

    // selected-expert evaluation
    {
        dim3 grid(B_ / EB_ROWS, C_);
        expert_kernel<<<grid, 256>>>(x, We1, be1, We2, be2, out + OUT_Y2);
    }
}

// round 8
// speedup vs baseline: 1.1209x; 1.0028x over previous
#include <cuda_runtime.h>
#include <cuda_bf16.h>
#include <math_constants.h>
#include <cstdint>

// Problem dims
#define B_    4096
#define N0_   2048
#define N1_   1000
#define N1P   1024
#define N1E   (N1P + 64)      // GEMM1 B-matrix rows incl. fused y0 (Wcat) block
#define N2_   500
#define N2P   512
#define N3_   100
#define C_    100
#define NDIM_ 3
#define NCLS_ 12

#define OUT_Y0 0
#define OUT_Y1 (B_ * NCLS_)
#define OUT_Y2 (B_ * NCLS_ + B_ * C_)

// ---------------- scratch ----------------
__device__ __nv_bfloat16 g_xhi[B_ * N0_];
__device__ __nv_bfloat16 g_xlo[B_ * N0_];
__device__ __nv_bfloat16 g_w1thi[N1E * N0_];
__device__ __nv_bfloat16 g_w1tlo[N1E * N0_];
__device__ __nv_bfloat16 g_h1hi[B_ * N1P];
__device__ __nv_bfloat16 g_h1lo[B_ * N1P];
__device__ __nv_bfloat16 g_w2thi[N2P * N1P];
__device__ __nv_bfloat16 g_w2tlo[N2P * N1P];
__device__ __nv_bfloat16 g_h2hi[B_ * N2P];
__device__ __nv_bfloat16 g_h2lo[B_ * N2P];
__device__ __nv_bfloat16 g_w3thi[128 * N2P];
__device__ __nv_bfloat16 g_w3tlo[128 * N2P];
__device__ int g_idx[B_];
__device__ int g_cnt[C_];
__device__ int g_off[C_ + 1];
__device__ int g_pos[C_];
__device__ int g_order[B_];

// ---------------- helpers ----------------
__device__ __forceinline__ uint32_t smem_u32(const void* p)
{
    uint32_t a;
    asm("{ .reg .u64 t; cvta.to.shared.u64 t, %1; cvt.u32.u64 %0, t; }" : "=r"(a) : "l"(p));
    return a;
}

__device__ __forceinline__ void cpasync16(uint32_t dst, const void* src)
{
    asm volatile("cp.async.cg.shared.global [%0], [%1], 16;" :: "r"(dst), "l"(src));
}

__device__ __forceinline__ void mma16816(float* c, const uint32_t* a, const uint32_t* b)
{
    asm volatile(
        "mma.sync.aligned.m16n8k16.row.col.f32.bf16.bf16.f32 "
        "{%0,%1,%2,%3}, {%4,%5,%6,%7}, {%8,%9}, {%0,%1,%2,%3};\n"
        : "+f"(c[0]), "+f"(c[1]), "+f"(c[2]), "+f"(c[3])
        : "r"(a[0]), "r"(a[1]), "r"(a[2]), "r"(a[3]), "r"(b[0]), "r"(b[1]));
}

__device__ __forceinline__ void ldsm4(uint32_t* r, uint32_t a)
{
    asm volatile("ldmatrix.sync.aligned.m8n8.x4.shared.b16 {%0,%1,%2,%3}, [%4];"
                 : "=r"(r[0]), "=r"(r[1]), "=r"(r[2]), "=r"(r[3]) : "r"(a));
}

// ---------------- preprocessing ----------------
__global__ void __launch_bounds__(256) split_kernel(
    const float* __restrict__ in, __nv_bfloat16* __restrict__ hi,
    __nv_bfloat16* __restrict__ lo, int n4)
{
    int i = blockIdx.x * 256 + threadIdx.x;
    if (i >= n4) return;
    float4 v = reinterpret_cast<const float4*>(in)[i];
    __nv_bfloat16 h0 = __float2bfloat16(v.x);
    __nv_bfloat16 h1 = __float2bfloat16(v.y);
    __nv_bfloat16 h2 = __float2bfloat16(v.z);
    __nv_bfloat16 h3 = __float2bfloat16(v.w);
    __nv_bfloat162 hp0; hp0.x = h0; hp0.y = h1;
    __nv_bfloat162 hp1; hp1.x = h2; hp1.y = h3;
    reinterpret_cast<__nv_bfloat162*>(hi)[i * 2 + 0] = hp0;
    reinterpret_cast<__nv_bfloat162*>(hi)[i * 2 + 1] = hp1;
    __nv_bfloat162 lp0, lp1;
    lp0.x = __float2bfloat16(v.x - __bfloat162float(h0));
    lp0.y = __float2bfloat16(v.y - __bfloat162float(h1));
    lp1.x = __float2bfloat16(v.z - __bfloat162float(h2));
    lp1.y = __float2bfloat16(v.w - __bfloat162float(h3));
    reinterpret_cast<__nv_bfloat162*>(lo)[i * 2 + 0] = lp0;
    reinterpret_cast<__nv_bfloat162*>(lo)[i * 2 + 1] = lp1;
}

// W [Kin][Nin] fp32 -> hi/lo [NP][KP] bf16 (transposed, zero-padded)
__global__ void __launch_bounds__(256) transpose_split_kernel(
    const float* __restrict__ in, __nv_bfloat16* __restrict__ hi,
    __nv_bfloat16* __restrict__ lo, int Kin, int Nin, int KP, int NP)
{
    __shared__ float t[32][33];
    int k0 = blockIdx.x * 32, n0 = blockIdx.y * 32;
    #pragma unroll
    for (int j = 0; j < 4; ++j) {
        int k = k0 + threadIdx.y + j * 8, n = n0 + threadIdx.x;
        t[threadIdx.y + j * 8][threadIdx.x] = (k < Kin && n < Nin) ? in[(size_t)k * Nin + n] : 0.f;
    }
    __syncthreads();
    #pragma unroll
    for (int j = 0; j < 4; ++j) {
        int n = n0 + threadIdx.y + j * 8, k = k0 + threadIdx.x;
        float v = t[threadIdx.x][threadIdx.y + j * 8];
        __nv_bfloat16 h = __float2bfloat16(v);
        hi[(size_t)n * KP + k] = h;
        lo[(size_t)n * KP + k] = __float2bfloat16(v - __bfloat162float(h));
    }
}

// ---------------- cp.async 3-stage split-bf16 mma GEMM (R5 shape) ----------------
// A: hi/lo [M][K] bf16, B: hi/lo [N][K] bf16.
// Block tile 128x64x32, 8 warps (4m x 2n), warp tile 32x32.
// D = Ah*Bh + Ah*Bl + Al*Bh.
// EPI=1: packed bf16 hi/lo out (stride strideH) for colBase<NB; fp32 y0 out
//        (12 cols, biasY, no relu) for colBase>=NB when Yf != nullptr.
// EPI=0: fp32 out, ldC stride, pair stores while gn+1 < Nvalid.
#define STAGE_SZ 30720            // A(hi,lo): 2*10240, B(hi,lo): 2*5120
#define A_LO_OFF 10240
#define B_HI_OFF 20480
#define B_LO_OFF 25600
#define SMEM_MMA (3 * STAGE_SZ)   // 92160

template <int EPI>
__global__ void __launch_bounds__(256, 2) mma_gemm_kernel(
    const __nv_bfloat16* __restrict__ Ahi, const __nv_bfloat16* __restrict__ Alo,
    const __nv_bfloat16* __restrict__ Bhi, const __nv_bfloat16* __restrict__ Blo,
    const float* __restrict__ bias, const float* __restrict__ biasY,
    float* __restrict__ Cf, __nv_bfloat16* __restrict__ Chi, __nv_bfloat16* __restrict__ Clo,
    float* __restrict__ Yf,
    int ldC, int Nvalid, int NB, int strideH, int K, int relu)
{
    extern __shared__ __align__(16) char smem[];
    const uint32_t sb = smem_u32(smem);

    const int tid  = threadIdx.x;
    const int lane = tid & 31;
    const int w    = tid >> 5;
    const int wm   = (w >> 1) * 32;
    const int wn   = (w & 1) * 32;
    const int rowBase = blockIdx.y * 128;
    const int colBase = blockIdx.x * 64;

    float acc[2][4][4];
    #pragma unroll
    for (int mt = 0; mt < 2; ++mt)
        #pragma unroll
        for (int nt = 0; nt < 4; ++nt)
            #pragma unroll
            for (int q = 0; q < 4; ++q) acc[mt][nt][q] = 0.f;

    const int KT = K >> 5;
    const int arow = tid >> 2;      // 0..63 (+64 second iter) for A; 0..63 for B
    const int aseg = tid & 3;

    auto load_stage = [&](int kt, int stage) {
        const uint32_t sbase = sb + stage * STAGE_SZ;
        #pragma unroll
        for (int it = 0; it < 2; ++it) {
            int row = arow + it * 64;
            uint32_t doff = row * 80 + aseg * 16;
            size_t goff = (size_t)(rowBase + row) * K + kt * 32 + aseg * 8;
            cpasync16(sbase + doff, Ahi + goff);
            cpasync16(sbase + A_LO_OFF + doff, Alo + goff);
        }
        {
            int row = arow;
            uint32_t doff = row * 80 + aseg * 16;
            size_t goff = (size_t)(colBase + row) * K + kt * 32 + aseg * 8;
            cpasync16(sbase + B_HI_OFF + doff, Bhi + goff);
            cpasync16(sbase + B_LO_OFF + doff, Blo + goff);
        }
    };

    load_stage(0, 0);
    asm volatile("cp.async.commit_group;" ::: "memory");
    load_stage(1, 1);
    asm volatile("cp.async.commit_group;" ::: "memory");

    int stage = 0;
    for (int kt = 0; kt < KT; ++kt) {
        if (kt + 1 < KT)
            asm volatile("cp.async.wait_group 1;" ::: "memory");
        else
            asm volatile("cp.async.wait_group 0;" ::: "memory");
        __syncthreads();

        if (kt + 2 < KT) {
            int ns = stage + 2; if (ns >= 3) ns -= 3;
            load_stage(kt + 2, ns);
            asm volatile("cp.async.commit_group;" ::: "memory");
        }

        const uint32_t sbase = sb + stage * STAGE_SZ;
        #pragma unroll
        for (int ks = 0; ks < 32; ks += 16) {
            uint32_t ah[2][4], al[2][4];
            #pragma unroll
            for (int mt = 0; mt < 2; ++mt) {
                uint32_t ad = sbase + (wm + mt * 16 + (lane & 15)) * 80
                            + (ks + (lane >> 4) * 8) * 2;
                ldsm4(ah[mt], ad);
                ldsm4(al[mt], ad + A_LO_OFF);
            }
            uint32_t bh0[4], bh1[4], bl0[4], bl1[4];
            {
                uint32_t bd = sbase + B_HI_OFF + (wn + lane) * 80 + ks * 2;
                ldsm4(bh0, bd);
                ldsm4(bh1, bd + 16);
                bd += (B_LO_OFF - B_HI_OFF);
                ldsm4(bl0, bd);
                ldsm4(bl1, bd + 16);
            }
            #pragma unroll
            for (int nt = 0; nt < 4; ++nt) {
                uint32_t bhp[2] = {bh0[nt], bh1[nt]};
                uint32_t blp[2] = {bl0[nt], bl1[nt]};
                #pragma unroll
                for (int mt = 0; mt < 2; ++mt) {
                    mma16816(acc[mt][nt], ah[mt], bhp);
                    mma16816(acc[mt][nt], ah[mt], blp);
                    mma16816(acc[mt][nt], al[mt], bhp);
                }
            }
        }
        __syncthreads();
        ++stage; if (stage == 3) stage = 0;
    }

    // epilogue
    const bool yblock = (EPI == 1) && (Yf != nullptr) && (colBase >= NB);
    #pragma unroll
    for (int mt = 0; mt < 2; ++mt) {
        #pragma unroll
        for (int nt = 0; nt < 4; ++nt) {
            int gm0 = rowBase + wm + mt * 16 + (lane >> 2);
            int gn  = colBase + wn + nt * 8 + (lane & 3) * 2;
            if (yblock) {
                int gy = gn - NB;
                if (gy < NCLS_) {
                    float b0 = biasY[gy], b1 = biasY[gy + 1];
                    #pragma unroll
                    for (int half = 0; half < 2; ++half) {
                        int gm = gm0 + half * 8;
                        float2 o = make_float2(acc[mt][nt][half * 2 + 0] + b0,
                                               acc[mt][nt][half * 2 + 1] + b1);
                        *reinterpret_cast<float2*>(Yf + (size_t)gm * NCLS_ + gy) = o;
                    }
                }
            } else {
                bool valid = gn < Nvalid;
                float b0 = valid ? bias[gn] : 0.f;
                float b1 = valid ? bias[gn + 1] : 0.f;
                #pragma unroll
                for (int half = 0; half < 2; ++half) {
                    int gm = gm0 + half * 8;
                    float v0 = valid ? (acc[mt][nt][half * 2 + 0] + b0) : 0.f;
                    float v1 = valid ? (acc[mt][nt][half * 2 + 1] + b1) : 0.f;
                    if (relu) { v0 = fmaxf(v0, 0.f); v1 = fmaxf(v1, 0.f); }
                    if (EPI == 1) {
                        __nv_bfloat16 h0 = __float2bfloat16(v0);
                        __nv_bfloat16 h1 = __float2bfloat16(v1);
                        __nv_bfloat162 hp; hp.x = h0; hp.y = h1;
                        *reinterpret_cast<__nv_bfloat162*>(Chi + (size_t)gm * strideH + gn) = hp;
                        __nv_bfloat162 lp;
                        lp.x = __float2bfloat16(v0 - __bfloat162float(h0));
                        lp.y = __float2bfloat16(v1 - __bfloat162float(h1));
                        *reinterpret_cast<__nv_bfloat162*>(Clo + (size_t)gm * strideH + gn) = lp;
                    } else {
                        if (gn + 1 < Nvalid) {
                            float2 o = make_float2(v0, v1);
                            *reinterpret_cast<float2*>(Cf + (size_t)gm * ldC + gn) = o;
                        }
                    }
                }
            }
        }
    }
}

// ---------------- argmax + counting sort ----------------
__global__ void zero_counts_kernel()
{
    int t = threadIdx.x;
    if (t < C_) g_cnt[t] = 0;
}

__global__ void argmax_kernel(const float* __restrict__ y1)
{
    const int warp = threadIdx.x >> 5, lane = threadIdx.x & 31;
    const int row = blockIdx.x * 4 + warp;
    const float* r = y1 + (size_t)row * C_;
    float bv = -CUDART_INF_F;
    int   bi = 0x7fffffff;
    for (int j = lane; j < C_; j += 32) {
        float v = r[j];
        if (v > bv || (v == bv && j < bi)) { bv = v; bi = j; }
    }
    #pragma unroll
    for (int o = 16; o; o >>= 1) {
        float ov = __shfl_down_sync(0xffffffffu, bv, o);
        int   oi = __shfl_down_sync(0xffffffffu, bi, o);
        if (ov > bv || (ov == bv && oi < bi)) { bv = ov; bi = oi; }
    }
    if (lane == 0) {
        g_idx[row] = bi;
        atomicAdd(&g_cnt[bi], 1);
    }
}

__global__ void prefix_kernel()
{
    if (threadIdx.x == 0) {
        int s = 0;
        for (int c = 0; c < C_; ++c) {
            g_off[c] = s;
            g_pos[c] = s;
            s += g_cnt[c];
        }
        g_off[C_] = s;
    }
}

__global__ void scatter_kernel()
{
    int b = blockIdx.x * 256 + threadIdx.x;
    int c = g_idx[b];
    int p = atomicAdd(&g_pos[c], 1);
    g_order[p] = b;
}

// ---------------- grouped expert kernel ----------------
#define EB_ROWS 32
#define EB_BK   32
#define NT      16

__global__ void __launch_bounds__(256) expert_kernel(
    const float* __restrict__ x,
    const float* __restrict__ We1, const float* __restrict__ be1,
    const float* __restrict__ We2, const float* __restrict__ be2,
    float* __restrict__ y2out)
{
    const int c     = blockIdx.y;
    const int chunk = blockIdx.x;
    const int start = g_off[c] + chunk * EB_ROWS;
    const int end   = g_off[c + 1];
    if (start >= end) return;

    __shared__ int   rs[EB_ROWS];
    __shared__ float Xs[EB_ROWS][EB_BK + 1];
    __shared__ float Ws[EB_BK * N3_ + 64];
    __shared__ float He[EB_ROWS][N3_ + 1];
    __shared__ float W2s[N3_ * NDIM_ + 4];

    const int tid  = threadIdx.x;
    const int lane = tid & 31;
    const int warp = tid >> 5;

    if (tid < EB_ROWS) rs[tid] = (start + tid < end) ? g_order[start + tid] : -1;
    for (int i = tid; i < N3_ * NDIM_; i += 256) W2s[i] = We2[(size_t)c * N3_ * NDIM_ + i];
    __syncthreads();

    const int nBase = warp * NT;
    float acc[NT];
    #pragma unroll
    for (int j = 0; j < NT; ++j) acc[j] = 0.f;

    const float* W1c = We1 + (size_t)c * N0_ * N3_;
    const float4* Ws4 = reinterpret_cast<const float4*>(Ws);

    for (int kt = 0; kt < N0_ / EB_BK; ++kt) {
        {
            int r  = tid >> 3;
            int k4 = (tid & 7) * 4;
            int rb = rs[r];
            float4 v = make_float4(0.f, 0.f, 0.f, 0.f);
            if (rb >= 0)
                v = *reinterpret_cast<const float4*>(&x[(size_t)rb * N0_ + kt * EB_BK + k4]);
            Xs[r][k4 + 0] = v.x; Xs[r][k4 + 1] = v.y;
            Xs[r][k4 + 2] = v.z; Xs[r][k4 + 3] = v.w;
        }
        {
            const float4* src = reinterpret_cast<const float4*>(W1c + (size_t)kt * EB_BK * N3_);
            float4* dst = reinterpret_cast<float4*>(Ws);
            #pragma unroll
            for (int i = 0; i < 4; ++i) {
                int id = tid + i * 256;
                if (id < (EB_BK * N3_) / 4) dst[id] = src[id];
            }
        }
        __syncthreads();

        #pragma unroll 4
        for (int k = 0; k < EB_BK; ++k) {
            float a = Xs[lane][k];
            #pragma unroll
            for (int j4 = 0; j4 < NT / 4; ++j4) {
                float4 wv = Ws4[(k * N3_ + nBase) / 4 + j4];
                acc[j4 * 4 + 0] += a * wv.x;
                acc[j4 * 4 + 1] += a * wv.y;
                acc[j4 * 4 + 2] += a * wv.z;
                acc[j4 * 4 + 3] += a * wv.w;
            }
        }
        __syncthreads();
    }

    #pragma unroll
    for (int j = 0; j < NT; ++j) {
        int n = nBase + j;
        if (n < N3_)
            He[lane][n] = fmaxf(acc[j] + be1[(size_t)c * N3_ + n], 0.f);
    }
    __syncthreads();

    if (tid < EB_ROWS * NDIM_) {
        int r = tid / NDIM_, d = tid % NDIM_;
        int rb = rs[r];
        if (rb >= 0) {
            float s = 0.f;
            #pragma unroll 4
            for (int k = 0; k < N3_; ++k) s += He[r][k] * W2s[k * NDIM_ + d];
            y2out[(size_t)rb * NDIM_ + d] = s + be2[(size_t)c * NDIM_ + d];
        }
    }
}

// ---------------- launch ----------------
extern "C" void kernel_launch(void* const* d_in, const int* in_sizes, int n_in,
                              void* d_out, int out_size)
{
    const float* x    = (const float*)d_in[0];
    const float* Wcat = (const float*)d_in[1];
    const float* bcat = (const float*)d_in[2];
    const float* Wb1  = (const float*)d_in[3];
    const float* bb1  = (const float*)d_in[4];
    const float* Wb2  = (const float*)d_in[5];
    const float* bb2  = (const float*)d_in[6];
    const float* Wb3  = (const float*)d_in[7];
    const float* bb3  = (const float*)d_in[8];
    const float* We1  = (const float*)d_in[9];
    const float* be1  = (const float*)d_in[10];
    const float* We2  = (const float*)d_in[11];
    const float* be2  = (const float*)d_in[12];
    float* out = (float*)d_out;

    __nv_bfloat16 *xhi, *xlo, *w1thi, *w1tlo, *h1hi, *h1lo;
    __nv_bfloat16 *w2thi, *w2tlo, *h2hi, *h2lo, *w3thi, *w3tlo;
    cudaGetSymbolAddress((void**)&xhi,   g_xhi);
    cudaGetSymbolAddress((void**)&xlo,   g_xlo);
    cudaGetSymbolAddress((void**)&w1thi, g_w1thi);
    cudaGetSymbolAddress((void**)&w1tlo, g_w1tlo);
    cudaGetSymbolAddress((void**)&h1hi,  g_h1hi);
    cudaGetSymbolAddress((void**)&h1lo,  g_h1lo);
    cudaGetSymbolAddress((void**)&w2thi, g_w2thi);
    cudaGetSymbolAddress((void**)&w2tlo, g_w2tlo);
    cudaGetSymbolAddress((void**)&h2hi,  g_h2hi);
    cudaGetSymbolAddress((void**)&h2lo,  g_h2lo);
    cudaGetSymbolAddress((void**)&w3thi, g_w3thi);
    cudaGetSymbolAddress((void**)&w3tlo, g_w3tlo);

    cudaFuncSetAttribute(mma_gemm_kernel<1>,
                         cudaFuncAttributeMaxDynamicSharedMemorySize, SMEM_MMA);
    cudaFuncSetAttribute(mma_gemm_kernel<0>,
                         cudaFuncAttributeMaxDynamicSharedMemorySize, SMEM_MMA);

    dim3 tblk(32, 8);
    const int BIG = 1 << 30;

    // 1: split x
    split_kernel<<<(B_ * N0_ / 4 + 255) / 256, 256>>>(x, xhi, xlo, B_ * N0_ / 4);
    // 2: Wb1^T -> w1t rows [0, 1024)
    transpose_split_kernel<<<dim3(N0_ / 32, N1P / 32), tblk>>>(Wb1, w1thi, w1tlo, N0_, N1_, N0_, N1P);
    // 3: Wcat^T -> w1t rows [1024, 1088)
    transpose_split_kernel<<<dim3(N0_ / 32, 64 / 32), tblk>>>(
        Wcat, w1thi + (size_t)N1P * N0_, w1tlo + (size_t)N1P * N0_, N0_, NCLS_, N0_, 64);
    // 4: GEMM1 (h1 + fused y0)  <-- profiled launch
    mma_gemm_kernel<1><<<dim3(N1E / 64, B_ / 128), 256, SMEM_MMA>>>(
        xhi, xlo, w1thi, w1tlo, bb1, bcat,
        nullptr, h1hi, h1lo, out + OUT_Y0,
        0, N1_, N1P, N1P, N0_, 1);
    // 5: Wb2^T
    transpose_split_kernel<<<dim3(N1P / 32, N2P / 32), tblk>>>(Wb2, w2thi, w2tlo, N1_, N2_, N1P, N2P);
    // 6: GEMM2
    mma_gemm_kernel<1><<<dim3(N2P / 64, B_ / 128), 256, SMEM_MMA>>>(
        h1hi, h1lo, w2thi, w2tlo, bb2, nullptr,
        nullptr, h2hi, h2lo, nullptr,
        0, N2_, BIG, N2P, N1P, 1);
    // 7: Wb3^T
    transpose_split_kernel<<<dim3(N2P / 32, 128 / 32), tblk>>>(Wb3, w3thi, w3tlo, N2_, C_, N2P, 128);
    // 8: GEMM3 -> y1 fp32
    mma_gemm_kernel<0><<<dim3(128 / 64, B_ / 128), 256, SMEM_MMA>>>(
        h2hi, h2lo, w3thi, w3tlo, bb3, nullptr,
        out + OUT_Y1, nullptr, nullptr, nullptr,
        C_, C_, BIG, 0, N2P, 0);

    // argmax + counting sort
    zero_counts_kernel<<<1, 128>>>();
    argmax_kernel<<<B_ / 4, 128>>>(out + OUT_Y1);
    prefix_kernel<<<1, 32>>>();
    scatter_kernel<<<B_ / 256, 256>>>();

    // selected-expert evaluation
    {
        dim3 grid(B_ / EB_ROWS, C_);
        expert_kernel<<<grid, 256>>>(x, We1, be1, We2, be2, out + OUT_Y2);
    }
}